// round 15
// baseline (speedup 1.0000x reference)
#include <cuda_runtime.h>
#include <cuda_fp16.h>

#define N_NODES   100000
#define HIDDEN    48
#define N_TRIPLES 2000000
#define ROW_PAD   64          // u/v rows padded to 64 halves = 128 B

__device__ __align__(16) __half g_u[N_NODES * ROW_PAD];    // fp16 u
__device__ __align__(16) __half g_v[N_NODES * ROW_PAD];    // fp16 v
__device__ __align__(16) float  g_agg[N_NODES * HIDDEN];   // zero-maintained
__device__ __align__(16) float  g_cnt[N_NODES];            // zero-maintained

// ---------------------------------------------------------------------------
// Fused prep+uv.
//  phase 1 (per block, conflict-free): C2[k][o] = sum_j W3[j][k]*Wu[o][48+j]
//    - sWu2 padded to stride 49 (49 mod 32 = 17, gcd 1 -> no conflicts)
//    - sW3[j*48+k] is warp-broadcast (k ~constant across a warp)
//  phase 2: u[n][o] = h[n]·Wu1[o]; v[n][o] = h[n]·C2[:,o] -> fp16, 128B rows.
//    4-row register tiling, blockDim (12, 32), 128-row tiles.
// ---------------------------------------------------------------------------
__global__ void uv_kernel(const float* __restrict__ h,
                          const float* __restrict__ Wu,
                          const float* __restrict__ W3) {
    __shared__ float4 sA[HIDDEN][12];     // Wu1^T quads: linear [k*48+o]
    __shared__ float4 sC[HIDDEN][12];     // C2 quads:    linear [k*48+o]
    __shared__ float  sh[128][49];        // phase1 scratch / phase2 h tile

    int tx = threadIdx.x;                  // 0..11
    int ty = threadIdx.y;                  // 0..31
    int tid = ty * 12 + tx;                // 0..383

    float* sW3  = &sh[0][0];               // [j*48+k], 2304 floats
    float* sWu2 = &sh[0][0] + 2304;        // [o*49+j], 2352 floats (padded)

    // ---- phase 1: stage W3 / Wu2 / Wu1^T ----
    for (int i = tid; i < HIDDEN * HIDDEN; i += 384) {
        sW3[i] = W3[i];
        int o = i / HIDDEN, j = i % HIDDEN;
        sWu2[o * 49 + j] = Wu[o * 2 * HIDDEN + HIDDEN + j];
        int k = i / HIDDEN, oo = i % HIDDEN;
        ((float*)sA)[i] = Wu[oo * 2 * HIDDEN + k];   // sA linear [k*48+oo]
    }
    __syncthreads();
    for (int i = tid; i < HIDDEN * HIDDEN; i += 384) {
        int k = i / HIDDEN, o = i % HIDDEN;
        float s = 0.f;
        #pragma unroll
        for (int j = 0; j < HIDDEN; j++)
            s = fmaf(sW3[j * HIDDEN + k], sWu2[o * 49 + j], s);
        ((float*)sC)[i] = s;
    }
    __syncthreads();

    // ---- phase 2: load h tile (overwrites phase-1 scratch) ----
    int rowBase = blockIdx.x * 128;
    for (int i = tid; i < 128 * 12; i += 384) {
        int r = i / 12, c4 = i % 12;
        int row = rowBase + r;
        float4 v = (row < N_NODES) ? ((const float4*)(h + row * HIDDEN))[c4]
                                   : make_float4(0.f, 0.f, 0.f, 0.f);
        sh[r][4*c4+0] = v.x; sh[r][4*c4+1] = v.y;
        sh[r][4*c4+2] = v.z; sh[r][4*c4+3] = v.w;
    }
    __syncthreads();

    int r0 = ty, r1 = ty + 32, r2 = ty + 64, r3 = ty + 96;
    float4 u0 = make_float4(0,0,0,0), u1 = u0, u2 = u0, u3 = u0;
    float4 v0 = u0, v1 = u0, v2 = u0, v3 = u0;
    #pragma unroll
    for (int k = 0; k < HIDDEN; k++) {
        float4 wa = sA[k][tx];
        float4 wc = sC[k][tx];
        float h0 = sh[r0][k];
        float h1 = sh[r1][k];
        float h2 = sh[r2][k];
        float h3 = sh[r3][k];
        u0.x = fmaf(h0, wa.x, u0.x); u0.y = fmaf(h0, wa.y, u0.y);
        u0.z = fmaf(h0, wa.z, u0.z); u0.w = fmaf(h0, wa.w, u0.w);
        u1.x = fmaf(h1, wa.x, u1.x); u1.y = fmaf(h1, wa.y, u1.y);
        u1.z = fmaf(h1, wa.z, u1.z); u1.w = fmaf(h1, wa.w, u1.w);
        u2.x = fmaf(h2, wa.x, u2.x); u2.y = fmaf(h2, wa.y, u2.y);
        u2.z = fmaf(h2, wa.z, u2.z); u2.w = fmaf(h2, wa.w, u2.w);
        u3.x = fmaf(h3, wa.x, u3.x); u3.y = fmaf(h3, wa.y, u3.y);
        u3.z = fmaf(h3, wa.z, u3.z); u3.w = fmaf(h3, wa.w, u3.w);
        v0.x = fmaf(h0, wc.x, v0.x); v0.y = fmaf(h0, wc.y, v0.y);
        v0.z = fmaf(h0, wc.z, v0.z); v0.w = fmaf(h0, wc.w, v0.w);
        v1.x = fmaf(h1, wc.x, v1.x); v1.y = fmaf(h1, wc.y, v1.y);
        v1.z = fmaf(h1, wc.z, v1.z); v1.w = fmaf(h1, wc.w, v1.w);
        v2.x = fmaf(h2, wc.x, v2.x); v2.y = fmaf(h2, wc.y, v2.y);
        v2.z = fmaf(h2, wc.z, v2.z); v2.w = fmaf(h2, wc.w, v2.w);
        v3.x = fmaf(h3, wc.x, v3.x); v3.y = fmaf(h3, wc.y, v3.y);
        v3.z = fmaf(h3, wc.z, v3.z); v3.w = fmaf(h3, wc.w, v3.w);
    }

    #pragma unroll
    for (int q = 0; q < 4; q++) {
        int row = rowBase + ty + 32 * q;
        if (row < N_NODES) {
            float4 uu = (q == 0) ? u0 : (q == 1) ? u1 : (q == 2) ? u2 : u3;
            float4 vv = (q == 0) ? v0 : (q == 1) ? v1 : (q == 2) ? v2 : v3;
            union { __half2 h2[2]; uint2 u; } cu, cv;
            cu.h2[0] = __floats2half2_rn(uu.x, uu.y);
            cu.h2[1] = __floats2half2_rn(uu.z, uu.w);
            cv.h2[0] = __floats2half2_rn(vv.x, vv.y);
            cv.h2[1] = __floats2half2_rn(vv.z, vv.w);
            ((uint2*)(g_u + row * ROW_PAD))[tx] = cu.u;
            ((uint2*)(g_v + row * ROW_PAD))[tx] = cv.u;
        }
    }
}

// ---------------------------------------------------------------------------
// Per-triple: direct idx/d reads + w compute + fp16 one-line gathers + hadd2
// + leaky*w + fp32 v4 RED + cnt atomic (lane 12). 8 triples per warp-iter.
// ---------------------------------------------------------------------------
__device__ __forceinline__ void process_triple(const int* __restrict__ idx,
                                               const float* __restrict__ d1a,
                                               const float* __restrict__ d2a,
                                               int t, int j) {
    int b = 3 * t;
    int c  = __ldg(idx + b);
    float d1 = __ldg(d1a + t);
    float d2 = __ldg(d2a + t);
    float w = 1.0f + 0.3f * (fabsf(d1 - d2) / (fmaxf(d1, d2) + 1e-8f));

    if (j < 12) {
        int n1 = __ldg(idx + b + 1);
        int n2 = __ldg(idx + b + 2);
        uint2 au = __ldg((const uint2*)(g_u + c  * ROW_PAD) + j);
        uint2 a1 = __ldg((const uint2*)(g_v + n1 * ROW_PAD) + j);
        uint2 a2 = __ldg((const uint2*)(g_v + n2 * ROW_PAD) + j);
        __half2 s0 = __hadd2(*(__half2*)&a1.x, *(__half2*)&a2.x);
        __half2 s1 = __hadd2(*(__half2*)&a1.y, *(__half2*)&a2.y);
        s0 = __hadd2(s0, *(__half2*)&au.x);
        s1 = __hadd2(s1, *(__half2*)&au.y);
        float2 f0 = __half22float2(s0);
        float2 f1 = __half22float2(s1);
        float w01 = 0.01f * w;
        float dx = fmaf(fminf(f0.x, 0.f), w01, fmaxf(f0.x, 0.f) * w);
        float dy = fmaf(fminf(f0.y, 0.f), w01, fmaxf(f0.y, 0.f) * w);
        float dz = fmaf(fminf(f1.x, 0.f), w01, fmaxf(f1.x, 0.f) * w);
        float dw = fmaf(fminf(f1.y, 0.f), w01, fmaxf(f1.y, 0.f) * w);
        float* dst = g_agg + c * HIDDEN + 4 * j;
        asm volatile("red.global.add.v4.f32 [%0], {%1, %2, %3, %4};"
                     :: "l"(dst), "f"(dx), "f"(dy), "f"(dz), "f"(dw)
                     : "memory");
    } else if (j == 12) {
        asm volatile("red.global.add.f32 [%0], %1;"
                     :: "l"(g_cnt + c), "f"(1.0f) : "memory");
    }
}

__global__ void __launch_bounds__(256) triple_kernel(const int* __restrict__ idx,
                                                     const float* __restrict__ d1a,
                                                     const float* __restrict__ d2a) {
    int gtid = blockIdx.x * blockDim.x + threadIdx.x;
    int warpId = gtid >> 5;
    int nWarps = (gridDim.x * blockDim.x) >> 5;
    int lane = threadIdx.x & 31;
    int half = lane >> 4;
    int j = lane & 15;

    // N_TRIPLES % 8 == 0: 8 consecutive triples per warp-iter, 4 chains in flight
    for (int base = warpId * 8; base < N_TRIPLES; base += nWarps * 8) {
        process_triple(idx, d1a, d2a, base + half, j);
        process_triple(idx, d1a, d2a, base + 2 + half, j);
        process_triple(idx, d1a, d2a, base + 4 + half, j);
        process_triple(idx, d1a, d2a, base + 6 + half, j);
    }
}

// ---------------------------------------------------------------------------
// out = LayerNorm(h + agg / sqrt(max(cnt,1))); re-zeroes agg/cnt (R12-exact).
// ---------------------------------------------------------------------------
__global__ void final_kernel(const float* __restrict__ h,
                             const float* __restrict__ gamma,
                             const float* __restrict__ beta,
                             float* __restrict__ out) {
    int tx = threadIdx.x;  // 0..15
    int ty = threadIdx.y;  // 0..15
    int row = blockIdx.x * 16 + ty;
    if (row >= N_NODES) return;

    float rs = rsqrtf(fmaxf(g_cnt[row], 1.0f));
    int base = row * HIDDEN + tx * 3;
    float x0 = h[base]     + g_agg[base]     * rs;
    float x1 = h[base + 1] + g_agg[base + 1] * rs;
    float x2 = h[base + 2] + g_agg[base + 2] * rs;

    g_agg[base] = 0.f; g_agg[base + 1] = 0.f; g_agg[base + 2] = 0.f;
    if (tx == 0) g_cnt[row] = 0.f;

    float s = x0 + x1 + x2;
    #pragma unroll
    for (int m = 8; m; m >>= 1) s += __shfl_xor_sync(0xffffffffu, s, m);
    float mu = s * (1.f / 48.f);

    float e0 = x0 - mu, e1 = x1 - mu, e2 = x2 - mu;
    float q = e0 * e0 + e1 * e1 + e2 * e2;
    #pragma unroll
    for (int m = 8; m; m >>= 1) q += __shfl_xor_sync(0xffffffffu, q, m);
    float inv = rsqrtf(q * (1.f / 48.f) + 1e-5f);

    int o = tx * 3;
    out[base]     = e0 * inv * gamma[o]     + beta[o];
    out[base + 1] = e1 * inv * gamma[o + 1] + beta[o + 1];
    out[base + 2] = e2 * inv * gamma[o + 2] + beta[o + 2];
}

// ---------------------------------------------------------------------------
extern "C" void kernel_launch(void* const* d_in, const int* in_sizes, int n_in,
                              void* d_out, int out_size) {
    const float* h     = (const float*)d_in[0];
    const int*   idx   = (const int*)d_in[1];
    const float* d1    = (const float*)d_in[2];
    const float* d2    = (const float*)d_in[3];
    const float* W3    = (const float*)d_in[4];
    const float* Wu    = (const float*)d_in[5];
    const float* gamma = (const float*)d_in[6];
    const float* beta  = (const float*)d_in[7];
    float* out = (float*)d_out;

    uv_kernel<<<(N_NODES + 127) / 128, dim3(12, 32)>>>(h, Wu, W3);
    triple_kernel<<<4096, 256>>>(idx, d1, d2);
    final_kernel<<<(N_NODES + 15) / 16, dim3(16, 16)>>>(h, gamma, beta, out);
}

// round 16
// speedup vs baseline: 1.1381x; 1.1381x over previous
#include <cuda_runtime.h>
#include <cuda_fp16.h>

#define N_NODES   100000
#define HIDDEN    48
#define N_TRIPLES 2000000
#define ROW_PAD   64          // u/v rows padded to 64 halves = 128 B

__device__ __align__(16) __half g_u[N_NODES * ROW_PAD];    // fp16 u
__device__ __align__(16) __half g_v[N_NODES * ROW_PAD];    // fp16 v
__device__ __align__(16) float  g_agg[N_NODES * HIDDEN];   // zero-maintained
__device__ __align__(16) float  g_cnt[N_NODES];            // zero-maintained
__device__ __align__(16) float  g_C2[HIDDEN * HIDDEN];

// ---------------------------------------------------------------------------
// C2[k][o] = sum_j W3[j][k] * Wu[o][48+j]   (48x48, trivial, separate kernel —
// fusing this into uv_kernel measured +38us twice; do not fuse)
// ---------------------------------------------------------------------------
__global__ void prep_kernel(const float* __restrict__ W3,
                            const float* __restrict__ Wu) {
    int i = blockIdx.x * blockDim.x + threadIdx.x;
    if (i < HIDDEN * HIDDEN) {
        int k = i / HIDDEN, o = i % HIDDEN;
        float s = 0.f;
        #pragma unroll
        for (int j = 0; j < HIDDEN; j++)
            s = fmaf(W3[j * HIDDEN + k], Wu[o * 2 * HIDDEN + HIDDEN + j], s);
        g_C2[i] = s;
    }
}

// ---------------------------------------------------------------------------
// u[n][o] = h[n]·Wu1[o];  v[n][o] = h[n]·C2[:,o]  -> both fp16, 128B rows.
// 4-row register tiling: blockDim (12, 32), 128-row tiles (R14-measured 29us).
// ---------------------------------------------------------------------------
__global__ void uv_kernel(const float* __restrict__ h,
                          const float* __restrict__ Wu) {
    __shared__ float4 sA[HIDDEN][12];
    __shared__ float4 sC[HIDDEN][12];
    __shared__ float  sh[128][49];

    int tx = threadIdx.x;                  // 0..11
    int ty = threadIdx.y;                  // 0..31
    int tid = ty * 12 + tx;

    for (int i = tid; i < HIDDEN * 12; i += 384) {
        int k = i / 12, c4 = i % 12;
        sA[k][c4] = make_float4(Wu[(4*c4+0) * 2*HIDDEN + k],
                                Wu[(4*c4+1) * 2*HIDDEN + k],
                                Wu[(4*c4+2) * 2*HIDDEN + k],
                                Wu[(4*c4+3) * 2*HIDDEN + k]);
        sC[k][c4] = ((const float4*)g_C2)[k * 12 + c4];
    }
    int rowBase = blockIdx.x * 128;
    for (int i = tid; i < 128 * 12; i += 384) {
        int r = i / 12, c4 = i % 12;
        int row = rowBase + r;
        float4 v = (row < N_NODES) ? ((const float4*)(h + row * HIDDEN))[c4]
                                   : make_float4(0.f, 0.f, 0.f, 0.f);
        sh[r][4*c4+0] = v.x; sh[r][4*c4+1] = v.y;
        sh[r][4*c4+2] = v.z; sh[r][4*c4+3] = v.w;
    }
    __syncthreads();

    int r0 = ty, r1 = ty + 32, r2 = ty + 64, r3 = ty + 96;
    float4 u0 = make_float4(0,0,0,0), u1 = u0, u2 = u0, u3 = u0;
    float4 v0 = u0, v1 = u0, v2 = u0, v3 = u0;
    #pragma unroll
    for (int k = 0; k < HIDDEN; k++) {
        float4 wa = sA[k][tx];
        float4 wc = sC[k][tx];
        float h0 = sh[r0][k];
        float h1 = sh[r1][k];
        float h2 = sh[r2][k];
        float h3 = sh[r3][k];
        u0.x = fmaf(h0, wa.x, u0.x); u0.y = fmaf(h0, wa.y, u0.y);
        u0.z = fmaf(h0, wa.z, u0.z); u0.w = fmaf(h0, wa.w, u0.w);
        u1.x = fmaf(h1, wa.x, u1.x); u1.y = fmaf(h1, wa.y, u1.y);
        u1.z = fmaf(h1, wa.z, u1.z); u1.w = fmaf(h1, wa.w, u1.w);
        u2.x = fmaf(h2, wa.x, u2.x); u2.y = fmaf(h2, wa.y, u2.y);
        u2.z = fmaf(h2, wa.z, u2.z); u2.w = fmaf(h2, wa.w, u2.w);
        u3.x = fmaf(h3, wa.x, u3.x); u3.y = fmaf(h3, wa.y, u3.y);
        u3.z = fmaf(h3, wa.z, u3.z); u3.w = fmaf(h3, wa.w, u3.w);
        v0.x = fmaf(h0, wc.x, v0.x); v0.y = fmaf(h0, wc.y, v0.y);
        v0.z = fmaf(h0, wc.z, v0.z); v0.w = fmaf(h0, wc.w, v0.w);
        v1.x = fmaf(h1, wc.x, v1.x); v1.y = fmaf(h1, wc.y, v1.y);
        v1.z = fmaf(h1, wc.z, v1.z); v1.w = fmaf(h1, wc.w, v1.w);
        v2.x = fmaf(h2, wc.x, v2.x); v2.y = fmaf(h2, wc.y, v2.y);
        v2.z = fmaf(h2, wc.z, v2.z); v2.w = fmaf(h2, wc.w, v2.w);
        v3.x = fmaf(h3, wc.x, v3.x); v3.y = fmaf(h3, wc.y, v3.y);
        v3.z = fmaf(h3, wc.z, v3.z); v3.w = fmaf(h3, wc.w, v3.w);
    }

    #pragma unroll
    for (int q = 0; q < 4; q++) {
        int row = rowBase + ty + 32 * q;
        if (row < N_NODES) {
            float4 uu = (q == 0) ? u0 : (q == 1) ? u1 : (q == 2) ? u2 : u3;
            float4 vv = (q == 0) ? v0 : (q == 1) ? v1 : (q == 2) ? v2 : v3;
            union { __half2 h2[2]; uint2 u; } cu, cv;
            cu.h2[0] = __floats2half2_rn(uu.x, uu.y);
            cu.h2[1] = __floats2half2_rn(uu.z, uu.w);
            cv.h2[0] = __floats2half2_rn(vv.x, vv.y);
            cv.h2[1] = __floats2half2_rn(vv.z, vv.w);
            ((uint2*)(g_u + row * ROW_PAD))[tx] = cu.u;
            ((uint2*)(g_v + row * ROW_PAD))[tx] = cv.u;
        }
    }
}

// ---------------------------------------------------------------------------
// Per-triple: direct idx/d reads + w compute + fp16 one-line gathers + hadd2
// + leaky*w + fp32 v4 RED + cnt atomic (lane 12). 8 triples per warp-iter
// (R15: 4 independent gather chains in flight).
// ---------------------------------------------------------------------------
__device__ __forceinline__ void process_triple(const int* __restrict__ idx,
                                               const float* __restrict__ d1a,
                                               const float* __restrict__ d2a,
                                               int t, int j) {
    int b = 3 * t;
    int c  = __ldg(idx + b);
    float d1 = __ldg(d1a + t);
    float d2 = __ldg(d2a + t);
    float w = 1.0f + 0.3f * (fabsf(d1 - d2) / (fmaxf(d1, d2) + 1e-8f));

    if (j < 12) {
        int n1 = __ldg(idx + b + 1);
        int n2 = __ldg(idx + b + 2);
        uint2 au = __ldg((const uint2*)(g_u + c  * ROW_PAD) + j);
        uint2 a1 = __ldg((const uint2*)(g_v + n1 * ROW_PAD) + j);
        uint2 a2 = __ldg((const uint2*)(g_v + n2 * ROW_PAD) + j);
        __half2 s0 = __hadd2(*(__half2*)&a1.x, *(__half2*)&a2.x);
        __half2 s1 = __hadd2(*(__half2*)&a1.y, *(__half2*)&a2.y);
        s0 = __hadd2(s0, *(__half2*)&au.x);
        s1 = __hadd2(s1, *(__half2*)&au.y);
        float2 f0 = __half22float2(s0);
        float2 f1 = __half22float2(s1);
        float w01 = 0.01f * w;
        float dx = fmaf(fminf(f0.x, 0.f), w01, fmaxf(f0.x, 0.f) * w);
        float dy = fmaf(fminf(f0.y, 0.f), w01, fmaxf(f0.y, 0.f) * w);
        float dz = fmaf(fminf(f1.x, 0.f), w01, fmaxf(f1.x, 0.f) * w);
        float dw = fmaf(fminf(f1.y, 0.f), w01, fmaxf(f1.y, 0.f) * w);
        float* dst = g_agg + c * HIDDEN + 4 * j;
        asm volatile("red.global.add.v4.f32 [%0], {%1, %2, %3, %4};"
                     :: "l"(dst), "f"(dx), "f"(dy), "f"(dz), "f"(dw)
                     : "memory");
    } else if (j == 12) {
        asm volatile("red.global.add.f32 [%0], %1;"
                     :: "l"(g_cnt + c), "f"(1.0f) : "memory");
    }
}

__global__ void __launch_bounds__(256) triple_kernel(const int* __restrict__ idx,
                                                     const float* __restrict__ d1a,
                                                     const float* __restrict__ d2a) {
    int gtid = blockIdx.x * blockDim.x + threadIdx.x;
    int warpId = gtid >> 5;
    int nWarps = (gridDim.x * blockDim.x) >> 5;
    int lane = threadIdx.x & 31;
    int half = lane >> 4;
    int j = lane & 15;

    for (int base = warpId * 8; base < N_TRIPLES; base += nWarps * 8) {
        process_triple(idx, d1a, d2a, base + half, j);
        process_triple(idx, d1a, d2a, base + 2 + half, j);
        process_triple(idx, d1a, d2a, base + 4 + half, j);
        process_triple(idx, d1a, d2a, base + 6 + half, j);
    }
}

// ---------------------------------------------------------------------------
// out = LayerNorm(h + agg / sqrt(max(cnt,1))); re-zeroes agg/cnt (R12-exact).
// ---------------------------------------------------------------------------
__global__ void final_kernel(const float* __restrict__ h,
                             const float* __restrict__ gamma,
                             const float* __restrict__ beta,
                             float* __restrict__ out) {
    int tx = threadIdx.x;  // 0..15
    int ty = threadIdx.y;  // 0..15
    int row = blockIdx.x * 16 + ty;
    if (row >= N_NODES) return;

    float rs = rsqrtf(fmaxf(g_cnt[row], 1.0f));
    int base = row * HIDDEN + tx * 3;
    float x0 = h[base]     + g_agg[base]     * rs;
    float x1 = h[base + 1] + g_agg[base + 1] * rs;
    float x2 = h[base + 2] + g_agg[base + 2] * rs;

    g_agg[base] = 0.f; g_agg[base + 1] = 0.f; g_agg[base + 2] = 0.f;
    if (tx == 0) g_cnt[row] = 0.f;

    float s = x0 + x1 + x2;
    #pragma unroll
    for (int m = 8; m; m >>= 1) s += __shfl_xor_sync(0xffffffffu, s, m);
    float mu = s * (1.f / 48.f);

    float e0 = x0 - mu, e1 = x1 - mu, e2 = x2 - mu;
    float q = e0 * e0 + e1 * e1 + e2 * e2;
    #pragma unroll
    for (int m = 8; m; m >>= 1) q += __shfl_xor_sync(0xffffffffu, q, m);
    float inv = rsqrtf(q * (1.f / 48.f) + 1e-5f);

    int o = tx * 3;
    out[base]     = e0 * inv * gamma[o]     + beta[o];
    out[base + 1] = e1 * inv * gamma[o + 1] + beta[o + 1];
    out[base + 2] = e2 * inv * gamma[o + 2] + beta[o + 2];
}

// ---------------------------------------------------------------------------
extern "C" void kernel_launch(void* const* d_in, const int* in_sizes, int n_in,
                              void* d_out, int out_size) {
    const float* h     = (const float*)d_in[0];
    const int*   idx   = (const int*)d_in[1];
    const float* d1    = (const float*)d_in[2];
    const float* d2    = (const float*)d_in[3];
    const float* W3    = (const float*)d_in[4];
    const float* Wu    = (const float*)d_in[5];
    const float* gamma = (const float*)d_in[6];
    const float* beta  = (const float*)d_in[7];
    float* out = (float*)d_out;

    prep_kernel<<<(HIDDEN * HIDDEN + 255) / 256, 256>>>(W3, Wu);
    uv_kernel<<<(N_NODES + 127) / 128, dim3(12, 32)>>>(h, Wu);
    triple_kernel<<<4096, 256>>>(idx, d1, d2);
    final_kernel<<<(N_NODES + 15) / 16, dim3(16, 16)>>>(h, gamma, beta, out);
}